// round 5
// baseline (speedup 1.0000x reference)
#include <cuda_runtime.h>
#include <stdint.h>

// EmbeddingDropout: out[r, :] = weight[x[r], :] * mask[x[r]]
// x: [16384] int32, weight: [50257, 512] f32, mask: [50257] f32.
//
// R5: stores via TMA bulk. Each block handles 16 consecutive rows =
// one contiguous 32 KB output range. Gather+scale into smem, then a single
// cp.async.bulk shared->global store. Reads: 8 independent LDG.128/thread.

#define D 512
#define D4 (D / 4)                 // 128 float4 per row
#define ROWS_PER_BLOCK 16
#define THREADS 256                // 8 warps, 2 rows per warp
#define BLOCK_BYTES (ROWS_PER_BLOCK * D * 4)   // 32768

__global__ __launch_bounds__(THREADS) void embedding_dropout_kernel(
    const int* __restrict__ x,           // [N]
    const float4* __restrict__ weight,   // [V, D4]
    const float* __restrict__ mask,      // [V]
    float4* __restrict__ out,            // [N, D4]
    int n_rows)
{
    __shared__ __align__(128) float4 buf[ROWS_PER_BLOCK * D4];  // 32 KB

    int block_row0 = blockIdx.x * ROWS_PER_BLOCK;
    int warp = threadIdx.x >> 5;
    int lane = threadIdx.x & 31;
    int r0 = block_row0 + 2 * warp;      // this warp's two rows
    int r1 = r0 + 1;

    bool full_block = (block_row0 + ROWS_PER_BLOCK) <= n_rows;

    if (full_block) {
        // Both index chains overlap; 8 independent LDG.128 per thread.
        int idx0 = __ldg(&x[r0]);
        int idx1 = __ldg(&x[r1]);
        float s0 = __ldg(&mask[idx0]);
        float s1 = __ldg(&mask[idx1]);

        const float4* w0 = weight + (size_t)idx0 * D4;
        const float4* w1 = weight + (size_t)idx1 * D4;

        float4 a[4], b[4];
        #pragma unroll
        for (int i = 0; i < 4; i++) a[i] = __ldg(&w0[lane + 32 * i]);
        #pragma unroll
        for (int i = 0; i < 4; i++) b[i] = __ldg(&w1[lane + 32 * i]);

        float4* sm0 = buf + (2 * warp) * D4;
        float4* sm1 = sm0 + D4;
        #pragma unroll
        for (int i = 0; i < 4; i++) {
            a[i].x *= s0; a[i].y *= s0; a[i].z *= s0; a[i].w *= s0;
            sm0[lane + 32 * i] = a[i];
        }
        #pragma unroll
        for (int i = 0; i < 4; i++) {
            b[i].x *= s1; b[i].y *= s1; b[i].z *= s1; b[i].w *= s1;
            sm1[lane + 32 * i] = b[i];
        }

        __syncthreads();
        // Order generic STS before async-proxy (TMA) reads of smem.
        asm volatile("fence.proxy.async.shared::cta;" ::: "memory");

        if (threadIdx.x == 0) {
            uint32_t smem_addr;
            asm("{ .reg .u64 t; cvta.to.shared.u64 t, %1; cvt.u32.u64 %0, t; }"
                : "=r"(smem_addr) : "l"(buf));
            void* gdst = (void*)(out + (size_t)block_row0 * D4);
            asm volatile(
                "cp.async.bulk.global.shared::cta.bulk_group [%0], [%1], %2;\n\t"
                "cp.async.bulk.commit_group;\n\t"
                :: "l"(gdst), "r"(smem_addr), "r"((uint32_t)BLOCK_BYTES)
                : "memory");
            // smem must stay valid until the bulk read completes.
            asm volatile("cp.async.bulk.wait_group.read 0;" ::: "memory");
        }
    } else {
        // Tail fallback: direct stores, per-row guard.
        for (int k = 0; k < 2; k++) {
            int r = r0 + k;
            if (r >= n_rows) break;
            int idx = __ldg(&x[r]);
            float s = __ldg(&mask[idx]);
            const float4* w = weight + (size_t)idx * D4;
            float4* o = out + (size_t)r * D4;
            #pragma unroll
            for (int i = 0; i < 4; i++) {
                float4 v = __ldg(&w[lane + 32 * i]);
                v.x *= s; v.y *= s; v.z *= s; v.w *= s;
                o[lane + 32 * i] = v;
            }
        }
    }
}

extern "C" void kernel_launch(void* const* d_in, const int* in_sizes, int n_in,
                              void* d_out, int out_size)
{
    // Identify inputs by element count: x=16384, weight=25731584, mask=50257.
    long long max_sz = -1, mid_sz = -1;
    int wi = -1, mi = -1, xi = -1;
    for (int i = 0; i < n_in; i++)
        if (in_sizes[i] > max_sz) { max_sz = in_sizes[i]; wi = i; }
    for (int i = 0; i < n_in; i++)
        if (i != wi && in_sizes[i] > mid_sz) { mid_sz = in_sizes[i]; mi = i; }
    for (int i = 0; i < n_in; i++)
        if (i != wi && i != mi) { xi = i; break; }

    const int*    x    = (const int*)d_in[xi];
    const float4* w    = (const float4*)d_in[wi];
    const float*  mask = (const float*)d_in[mi];
    float4*       out  = (float4*)d_out;
    int n_rows = in_sizes[xi];

    int blocks = (n_rows + ROWS_PER_BLOCK - 1) / ROWS_PER_BLOCK;
    embedding_dropout_kernel<<<blocks, THREADS>>>(x, w, mask, out, n_rows);
}